// round 3
// baseline (speedup 1.0000x reference)
#include <cuda_runtime.h>
#include <math.h>

// Problem shapes (fixed by dataset): B=8192, S=6, H=1024
#define MAXB 8192
#define MAXH 1024

// Scratch (device globals: no allocations allowed in kernel_launch)
__device__ float g_cond[(size_t)MAXB * 2 * MAXH];   // [B, 2H]  (mean||max pools)
__device__ float g_Wf[(size_t)2 * MAXH * MAXH];     // W' = Wq @ Wk^T   [2H, H]
__device__ float g_cp[MAXH];                        // (bq+bp) @ Wk^T
__device__ float g_pp[MAXH];                        // Wp @ Wk^T
__device__ float g_r[(size_t)MAXB * MAXH];          // r = cond@W' + c' + gate*p'
__device__ float g_u[(size_t)MAXB * MAXH];          // u = sum_s w_s * ES[b,s,:]

// ---------------------------------------------------------------------------
// K0: pooling pass. One thread per (b,h): mean & max over S=6 rows.
// ---------------------------------------------------------------------------
__global__ void pool_kernel(const float* __restrict__ ES, float* __restrict__ cond,
                            int B, int S, int H) {
    int idx = blockIdx.x * blockDim.x + threadIdx.x;
    if (idx >= B * H) return;
    int b = idx / H, h = idx - b * H;
    const float* p = ES + (size_t)b * S * H + h;
    float v = p[0];
    float sum = v, mx = v;
    for (int s = 1; s < S; s++) {
        v = p[(size_t)s * H];
        sum += v;
        mx = fmaxf(mx, v);
    }
    float inv = 1.0f / (float)S;
    cond[(size_t)b * 2 * H + h] = sum * inv;
    cond[(size_t)b * 2 * H + H + h] = mx;
}

// ---------------------------------------------------------------------------
// K1b: c'[j] = sum_k (bq+bp)[k] * Wk[j,k];  p'[j] = sum_k Wp[k] * Wk[j,k]
// One warp per output j.
// ---------------------------------------------------------------------------
__global__ void fold_kernel(const float* __restrict__ Wk, const float* __restrict__ bq,
                            const float* __restrict__ bp, const float* __restrict__ Wp,
                            float* __restrict__ cp, float* __restrict__ pp, int H) {
    int gw = (blockIdx.x * blockDim.x + threadIdx.x) >> 5;
    int lane = threadIdx.x & 31;
    if (gw >= H) return;
    const float* row = Wk + (size_t)gw * H;
    float ac = 0.f, ap = 0.f;
    for (int k = lane * 4; k < H; k += 128) {
        float4 w  = *(const float4*)(row + k);
        float4 q  = *(const float4*)(bq + k);
        float4 p  = *(const float4*)(bp + k);
        float4 wp = *(const float4*)(Wp + k);
        ac += (q.x + p.x) * w.x + (q.y + p.y) * w.y + (q.z + p.z) * w.z + (q.w + p.w) * w.w;
        ap += wp.x * w.x + wp.y * w.y + wp.z * w.z + wp.w * w.w;
    }
    for (int o = 16; o; o >>= 1) {
        ac += __shfl_xor_sync(0xFFFFFFFFu, ac, o);
        ap += __shfl_xor_sync(0xFFFFFFFFu, ap, o);
    }
    if (lane == 0) { cp[gw] = ac; pp[gw] = ap; }
}

// ---------------------------------------------------------------------------
// Tiled fp32 SGEMM: C[M,N] = A[M,K] @ op(B)
//   BT=false: B is [K,N] row-major (NN)
//   BT=true : B is [N,K] row-major (NT, i.e. C = A @ B^T)
// EPI: 0 none | 1 C += e0[n] + gate[m]*e1[n] | 2 C += e0[n]
// 128x128 block tile, BK=16, 8x8 per thread, 256 threads.
// All of M,N multiples of 128 and K multiple of 16 (guaranteed by shapes).
// ---------------------------------------------------------------------------
template<bool BT, int EPI>
__global__ __launch_bounds__(256)
void sgemm_kernel(const float* __restrict__ A, const float* __restrict__ B,
                  float* __restrict__ C, int M, int N, int K,
                  const float* __restrict__ e0, const float* __restrict__ e1,
                  const float* __restrict__ gate) {
    constexpr int BM = 128, BN = 128, BK = 16, PAD = 4;
    __shared__ float As[BK][BM + PAD];
    __shared__ float Bs[BK][BN + PAD];
    const int tid = threadIdx.x;
    const int rowBase = blockIdx.y * BM;
    const int colBase = blockIdx.x * BN;
    const int tx = tid & 15, ty = tid >> 4;
    const int r4 = tid >> 2;          // 0..63
    const int c4 = (tid & 3) << 2;    // 0,4,8,12
    const int bR = tid >> 5;          // 0..7
    const int bC = (tid & 31) << 2;   // 0..124

    float acc[8][8] = {};

    for (int k0 = 0; k0 < K; k0 += BK) {
        // A tile (transposed into smem)
        #pragma unroll
        for (int p = 0; p < BM; p += 64) {
            float4 v = *(const float4*)(A + (size_t)(rowBase + r4 + p) * K + (k0 + c4));
            As[c4 + 0][r4 + p] = v.x;
            As[c4 + 1][r4 + p] = v.y;
            As[c4 + 2][r4 + p] = v.z;
            As[c4 + 3][r4 + p] = v.w;
        }
        // B tile
        if (BT) {
            #pragma unroll
            for (int p = 0; p < BN; p += 64) {
                float4 v = *(const float4*)(B + (size_t)(colBase + r4 + p) * K + (k0 + c4));
                Bs[c4 + 0][r4 + p] = v.x;
                Bs[c4 + 1][r4 + p] = v.y;
                Bs[c4 + 2][r4 + p] = v.z;
                Bs[c4 + 3][r4 + p] = v.w;
            }
        } else {
            #pragma unroll
            for (int p = 0; p < BK; p += 8) {
                float4 v = *(const float4*)(B + (size_t)(k0 + bR + p) * N + (colBase + bC));
                *(float4*)&Bs[bR + p][bC] = v;
            }
        }
        __syncthreads();

        #pragma unroll
        for (int kk = 0; kk < BK; kk++) {
            float a[8], bb[8];
            *(float4*)(a)      = *(const float4*)&As[kk][ty * 8];
            *(float4*)(a + 4)  = *(const float4*)&As[kk][ty * 8 + 4];
            *(float4*)(bb)     = *(const float4*)&Bs[kk][tx * 8];
            *(float4*)(bb + 4) = *(const float4*)&Bs[kk][tx * 8 + 4];
            #pragma unroll
            for (int i = 0; i < 8; i++)
                #pragma unroll
                for (int j = 0; j < 8; j++)
                    acc[i][j] = fmaf(a[i], bb[j], acc[i][j]);
        }
        __syncthreads();
    }

    #pragma unroll
    for (int i = 0; i < 8; i++) {
        int row = rowBase + ty * 8 + i;
        float g = (EPI == 1) ? gate[row] : 0.f;
        #pragma unroll
        for (int j = 0; j < 8; j += 4) {
            int col = colBase + tx * 8 + j;
            float4 v = { acc[i][j], acc[i][j + 1], acc[i][j + 2], acc[i][j + 3] };
            if (EPI == 1) {
                v.x += e0[col + 0] + g * e1[col + 0];
                v.y += e0[col + 1] + g * e1[col + 1];
                v.z += e0[col + 2] + g * e1[col + 2];
                v.w += e0[col + 3] + g * e1[col + 3];
            } else if (EPI == 2) {
                v.x += e0[col + 0];
                v.y += e0[col + 1];
                v.z += e0[col + 2];
                v.w += e0[col + 3];
            }
            *(float4*)(C + (size_t)row * N + col) = v;
        }
    }
}

// ---------------------------------------------------------------------------
// K3: per-batch scores -> softmax -> weights/entropy out, u = sum_s w_s ES[b,s,:]
// One block (256 threads) per batch row b. S=6, H=1024 hard requirements.
// ---------------------------------------------------------------------------
__global__ __launch_bounds__(256)
void attend_kernel(const float* __restrict__ ES, const float* __restrict__ r,
                   const float* __restrict__ sbias,
                   float* __restrict__ w_out, float* __restrict__ ent_out,
                   float* __restrict__ u_out) {
    const int b = blockIdx.x;
    const int tid = threadIdx.x;
    __shared__ float es_sh[6 * 1024];
    __shared__ float red[6][8];

    // Stage ES[b] (24 KB) into smem
    const float4* src = (const float4*)(ES + (size_t)b * 6 * 1024);
    float4* dst = (float4*)es_sh;
    #pragma unroll
    for (int i = 0; i < 6; i++) dst[tid + i * 256] = src[tid + i * 256];

    float4 rv = ((const float4*)(r + (size_t)b * 1024))[tid];
    __syncthreads();

    float4 ev[6];
    float sc[6];
    #pragma unroll
    for (int s = 0; s < 6; s++) {
        ev[s] = *(const float4*)&es_sh[s * 1024 + tid * 4];
        sc[s] = ev[s].x * rv.x + ev[s].y * rv.y + ev[s].z * rv.z + ev[s].w * rv.w;
    }
    #pragma unroll
    for (int s = 0; s < 6; s++)
        for (int o = 16; o; o >>= 1) sc[s] += __shfl_xor_sync(0xFFFFFFFFu, sc[s], o);
    if ((tid & 31) == 0) {
        #pragma unroll
        for (int s = 0; s < 6; s++) red[s][tid >> 5] = sc[s];
    }
    __syncthreads();

    // All threads redundantly finish the reduction + softmax (cheap, deterministic)
    float w[6], m = -1e30f;
    #pragma unroll
    for (int s = 0; s < 6; s++) {
        float t = sbias[s];
        #pragma unroll
        for (int wp = 0; wp < 8; wp++) t += red[s][wp];
        w[s] = t;
        m = fmaxf(m, t);
    }
    float Z = 0.f;
    #pragma unroll
    for (int s = 0; s < 6; s++) { w[s] = expf(w[s] - m); Z += w[s]; }
    float inv = 1.f / Z;
    float ent = 0.f;
    #pragma unroll
    for (int s = 0; s < 6; s++) {
        w[s] *= inv;
        ent -= w[s] * logf(w[s] + 1e-8f);
    }
    if (tid == 0) {
        #pragma unroll
        for (int s = 0; s < 6; s++) w_out[(size_t)b * 6 + s] = w[s];
        ent_out[b] = ent;
    }

    float4 u;
    u.x = w[0]*ev[0].x; u.y = w[0]*ev[0].y; u.z = w[0]*ev[0].z; u.w = w[0]*ev[0].w;
    #pragma unroll
    for (int s = 1; s < 6; s++) {
        u.x += w[s]*ev[s].x; u.y += w[s]*ev[s].y; u.z += w[s]*ev[s].z; u.w += w[s]*ev[s].w;
    }
    ((float4*)(u_out + (size_t)b * 1024))[tid] = u;
}

// ---------------------------------------------------------------------------
// Launch: pool -> fold -> W' = Wq@Wk^T -> r = cond@W' (+c' +gate*p')
//         -> attend (weights, entropy, u) -> fused = u@Wv + bv
// ---------------------------------------------------------------------------
extern "C" void kernel_launch(void* const* d_in, const int* in_sizes, int n_in,
                              void* d_out, int out_size) {
    const float* ES    = (const float*)d_in[0];
    // d_in[1] gene_context: unused by the reference
    const float* gate  = (const float*)d_in[2];
    const float* Wk    = (const float*)d_in[3];
    // d_in[4] bk: per-batch constant shift of all S scores -> cancels in softmax
    const float* Wv    = (const float*)d_in[5];
    const float* bv    = (const float*)d_in[6];
    const float* Wq    = (const float*)d_in[7];
    const float* bq    = (const float*)d_in[8];
    const float* Wp    = (const float*)d_in[9];
    const float* bp    = (const float*)d_in[10];
    const float* sbias = (const float*)d_in[11];

    const int B = in_sizes[2];    // pathogenicity_gate is [B,1]
    const int H = in_sizes[4];    // bk is [H]
    const int S = in_sizes[11];   // source_bias is [S]

    float* out       = (float*)d_out;
    float* out_fused = out;                         // [B,H]
    float* out_w     = out + (size_t)B * H;         // [B,S]
    float* out_ent   = out_w + (size_t)B * S;       // [B,1]

    float *cond, *Wf, *cp, *pp, *rr, *uu;
    cudaGetSymbolAddress((void**)&cond, g_cond);
    cudaGetSymbolAddress((void**)&Wf,   g_Wf);
    cudaGetSymbolAddress((void**)&cp,   g_cp);
    cudaGetSymbolAddress((void**)&pp,   g_pp);
    cudaGetSymbolAddress((void**)&rr,   g_r);
    cudaGetSymbolAddress((void**)&uu,   g_u);

    // K0: pools
    pool_kernel<<<(B * H + 255) / 256, 256>>>(ES, cond, B, S, H);
    // K1b: bias folds through Wk^T
    fold_kernel<<<(H * 32 + 255) / 256, 256>>>(Wk, bq, bp, Wp, cp, pp, H);
    // K1: W' = Wq @ Wk^T   [2H, H]
    {
        dim3 grid(H / 128, (2 * H) / 128);
        sgemm_kernel<true, 0><<<grid, 256>>>(Wq, Wk, Wf, 2 * H, H, H,
                                             nullptr, nullptr, nullptr);
    }
    // K2: r = cond @ W' + c' + gate * p'   [B, H]
    {
        dim3 grid(H / 128, B / 128);
        sgemm_kernel<false, 1><<<grid, 256>>>(cond, Wf, rr, B, H, 2 * H,
                                              cp, pp, gate);
    }
    // K3: scores/softmax/entropy/u
    attend_kernel<<<B, 256>>>(ES, rr, sbias, out_w, out_ent, uu);
    // K4: fused = u @ Wv + bv   [B, H]
    {
        dim3 grid(H / 128, B / 128);
        sgemm_kernel<false, 2><<<grid, 256>>>(uu, Wv, out_fused, B, H, H,
                                              bv, nullptr, nullptr);
    }
}

// round 6
// speedup vs baseline: 2.0723x; 2.0723x over previous
#include <cuda_runtime.h>
#include <cuda_bf16.h>
#include <math.h>
#include <stdint.h>

#define MAXB 8192
#define MAXH 1024
typedef __nv_bfloat16 bf16;

// Scratch (device globals — no allocation allowed)
__device__ bf16 g_cond_hi[(size_t)MAXB * 2 * MAXH];
__device__ bf16 g_cond_lo[(size_t)MAXB * 2 * MAXH];
__device__ bf16 g_Wk_hi[(size_t)MAXH * MAXH];
__device__ bf16 g_Wk_lo[(size_t)MAXH * MAXH];
__device__ bf16 g_Wq_hi[(size_t)2 * MAXH * MAXH];
__device__ bf16 g_Wq_lo[(size_t)2 * MAXH * MAXH];
__device__ bf16 g_Wt_hi[(size_t)MAXH * 2 * MAXH];   // Wt[h, i] = W'[i, h]
__device__ bf16 g_Wt_lo[(size_t)MAXH * 2 * MAXH];
__device__ bf16 g_WvT_hi[(size_t)MAXH * MAXH];
__device__ bf16 g_WvT_lo[(size_t)MAXH * MAXH];
__device__ bf16 g_u_hi[(size_t)MAXB * MAXH];
__device__ bf16 g_u_lo[(size_t)MAXB * MAXH];
__device__ float g_r[(size_t)MAXB * MAXH];
__device__ float g_cp[MAXH];
__device__ float g_pp[MAXH];

__device__ __forceinline__ uint32_t smem_u32(const void* p) {
    uint32_t a;
    asm("{ .reg .u64 t; cvta.to.shared.u64 t, %1; cvt.u32.u64 %0, t; }" : "=r"(a) : "l"(p));
    return a;
}
__device__ __forceinline__ void bf16_split(float v, bf16& h, bf16& l) {
    h = __float2bfloat16(v);
    l = __float2bfloat16(v - __bfloat162float(h));
}

#define MMA16816(d, a, b0, b1) \
    asm volatile("mma.sync.aligned.m16n8k16.row.col.f32.bf16.bf16.f32 " \
        "{%0,%1,%2,%3}, {%4,%5,%6,%7}, {%8,%9}, {%0,%1,%2,%3};" \
        : "+f"((d)[0]), "+f"((d)[1]), "+f"((d)[2]), "+f"((d)[3]) \
        : "r"((a)[0]), "r"((a)[1]), "r"((a)[2]), "r"((a)[3]), "r"(b0), "r"(b1))

#define CP_ASYNC16(sa, gp) \
    asm volatile("cp.async.cg.shared.global [%0], [%1], 16;" :: "r"(sa), "l"(gp) : "memory")
#define CP_COMMIT() asm volatile("cp.async.commit_group;" ::: "memory")

// ---------------------------------------------------------------------------
// Producers
// ---------------------------------------------------------------------------
__global__ void pool_kernel(const float* __restrict__ ES, bf16* __restrict__ ch,
                            bf16* __restrict__ cl, int B, int S, int H) {
    int idx = blockIdx.x * blockDim.x + threadIdx.x;
    if (idx >= B * H) return;
    int b = idx / H, h = idx - b * H;
    const float* p = ES + (size_t)b * S * H + h;
    float v = p[0], sum = v, mx = v;
    for (int s = 1; s < S; s++) { v = p[(size_t)s * H]; sum += v; mx = fmaxf(mx, v); }
    float mean = sum * (1.0f / (float)S);
    size_t o0 = (size_t)b * 2 * H + h, o1 = o0 + H;
    bf16 hh, ll;
    bf16_split(mean, hh, ll); ch[o0] = hh; cl[o0] = ll;
    bf16_split(mx,   hh, ll); ch[o1] = hh; cl[o1] = ll;
}

__global__ void split_kernel(const float* __restrict__ x, bf16* __restrict__ hi,
                             bf16* __restrict__ lo, int n) {
    int i = blockIdx.x * blockDim.x + threadIdx.x;
    if (i >= n) return;
    bf16 h, l; bf16_split(x[i], h, l);
    hi[i] = h; lo[i] = l;
}

__global__ void transpose_split_kernel(const float* __restrict__ in, bf16* __restrict__ hi,
                                       bf16* __restrict__ lo, int H) {
    __shared__ float t[32][33];
    int x = blockIdx.x * 32 + threadIdx.x;
    int y0 = blockIdx.y * 32;
    #pragma unroll
    for (int i = 0; i < 32; i += 8)
        t[threadIdx.y + i][threadIdx.x] = in[(size_t)(y0 + threadIdx.y + i) * H + x];
    __syncthreads();
    int ox = y0 + threadIdx.x;
    #pragma unroll
    for (int i = 0; i < 32; i += 8) {
        float v = t[threadIdx.x][threadIdx.y + i];
        bf16 h, l; bf16_split(v, h, l);
        size_t o = (size_t)(blockIdx.x * 32 + threadIdx.y + i) * H + ox;
        hi[o] = h; lo[o] = l;
    }
}

__global__ void fold_kernel(const float* __restrict__ Wk, const float* __restrict__ bq,
                            const float* __restrict__ bp, const float* __restrict__ Wp,
                            float* __restrict__ cp, float* __restrict__ pp, int H) {
    int gw = (blockIdx.x * blockDim.x + threadIdx.x) >> 5;
    int lane = threadIdx.x & 31;
    if (gw >= H) return;
    const float* row = Wk + (size_t)gw * H;
    float ac = 0.f, ap = 0.f;
    for (int k = lane * 4; k < H; k += 128) {
        float4 w  = *(const float4*)(row + k);
        float4 q  = *(const float4*)(bq + k);
        float4 p  = *(const float4*)(bp + k);
        float4 wp = *(const float4*)(Wp + k);
        ac += (q.x + p.x) * w.x + (q.y + p.y) * w.y + (q.z + p.z) * w.z + (q.w + p.w) * w.w;
        ap += wp.x * w.x + wp.y * w.y + wp.z * w.z + wp.w * w.w;
    }
    for (int o = 16; o; o >>= 1) {
        ac += __shfl_xor_sync(0xFFFFFFFFu, ac, o);
        ap += __shfl_xor_sync(0xFFFFFFFFu, ap, o);
    }
    if (lane == 0) { cp[gw] = ac; pp[gw] = ap; }
}

// ---------------------------------------------------------------------------
// bf16x3 tensor-core GEMM:  D[m,n] = sum_k A[m,k]*B[n,k]
// A = Ah+Al, B = Bh+Bl (bf16 splits, K-major [rows][K]).
// 128x128x32 block tile, 256 thr (4x2 warps, 32x64 warp tile), cp.async x2 stage.
// EPI 0: bf16-split D -> (C0,C1) | 1: C0 = D + e0[n] + gate[m]*e1[n] | 2: C0 = D + e0[n]
// ---------------------------------------------------------------------------
#define SROW 40            // bf16 elems per smem row (32 data + 8 pad) = 80 B
#define ARR  (128 * SROW)  // elems per array
#define STG  (4 * ARR)     // elems per stage

template<int EPI>
__global__ __launch_bounds__(256)
void mma_gemm(const bf16* __restrict__ Ah, const bf16* __restrict__ Al,
              const bf16* __restrict__ Bh, const bf16* __restrict__ Bl,
              void* __restrict__ C0v, void* __restrict__ C1v, int ldc, int K,
              const float* __restrict__ e0, const float* __restrict__ e1,
              const float* __restrict__ gate) {
    extern __shared__ bf16 sm[];
    const int tid = threadIdx.x;
    const int lane = tid & 31, wid = tid >> 5;
    const int warpM = wid >> 1, warpN = wid & 1;
    const int rowBase = blockIdx.y * 128, colBase = blockIdx.x * 128;
    const int g = lane >> 2, tg = lane & 3;
    const uint32_t smb = smem_u32(sm);

    float acc[2][8][4] = {};

    const bf16* srcs[4] = { Ah, Al, Bh, Bl };
    const int ldrow  = tid >> 2;           // 0..63
    const int ldrow2 = (tid + 256) >> 2;   // 64..127
    const int ldc16 = tid & 3;

    // --- stage loader: 4 arrays x 128 rows x 4 x 16B chunks, 8 per thread ---
    #define LOAD_STAGE(s, k0) do {                                                   \
        _Pragma("unroll")                                                            \
        for (int a_ = 0; a_ < 4; a_++) {                                             \
            const bf16* src_ = srcs[a_];                                             \
            int base_ = (a_ < 2) ? rowBase : colBase;                                \
            uint32_t sa_ = smb + (uint32_t)((s) * STG + a_ * ARR) * 2u;              \
            const bf16* g1 = src_ + (size_t)(base_ + ldrow)  * K + (k0) + ldc16 * 8; \
            const bf16* g2 = src_ + (size_t)(base_ + ldrow2) * K + (k0) + ldc16 * 8; \
            CP_ASYNC16(sa_ + (uint32_t)(ldrow  * SROW + ldc16 * 8) * 2u, g1);        \
            CP_ASYNC16(sa_ + (uint32_t)(ldrow2 * SROW + ldc16 * 8) * 2u, g2);        \
        }                                                                            \
        CP_COMMIT();                                                                 \
    } while (0)

    const int nch = K >> 5;   // K / 32
    LOAD_STAGE(0, 0);
    LOAD_STAGE(1, 32);

    for (int c = 0; c < nch; c++) {
        const int s = c & 1;
        if (c >= nch - 1) asm volatile("cp.async.wait_group 0;" ::: "memory");
        else              asm volatile("cp.async.wait_group 1;" ::: "memory");
        __syncthreads();

        const bf16* smAh = sm + s * STG;
        const bf16* smAl = smAh + ARR;
        const bf16* smBh = smAl + ARR;
        const bf16* smBl = smBh + ARR;

        #pragma unroll
        for (int kk = 0; kk < 32; kk += 16) {
            uint32_t ah[2][4], al[2][4];
            #pragma unroll
            for (int mt = 0; mt < 2; mt++) {
                int R = warpM * 32 + mt * 16;
                int o0 = (R + g) * SROW + kk + tg * 2;
                int o1 = (R + g + 8) * SROW + kk + tg * 2;
                ah[mt][0] = *(const uint32_t*)(smAh + o0);
                ah[mt][1] = *(const uint32_t*)(smAh + o1);
                ah[mt][2] = *(const uint32_t*)(smAh + o0 + 8);
                ah[mt][3] = *(const uint32_t*)(smAh + o1 + 8);
                al[mt][0] = *(const uint32_t*)(smAl + o0);
                al[mt][1] = *(const uint32_t*)(smAl + o1);
                al[mt][2] = *(const uint32_t*)(smAl + o0 + 8);
                al[mt][3] = *(const uint32_t*)(smAl + o1 + 8);
            }
            #pragma unroll
            for (int nt = 0; nt < 8; nt++) {
                int C = warpN * 64 + nt * 8;
                int ob = (C + g) * SROW + kk + tg * 2;
                uint32_t bh0 = *(const uint32_t*)(smBh + ob);
                uint32_t bh1 = *(const uint32_t*)(smBh + ob + 8);
                uint32_t bl0 = *(const uint32_t*)(smBl + ob);
                uint32_t bl1 = *(const uint32_t*)(smBl + ob + 8);
                #pragma unroll
                for (int mt = 0; mt < 2; mt++) {
                    MMA16816(acc[mt][nt], ah[mt], bh0, bh1);
                    MMA16816(acc[mt][nt], ah[mt], bl0, bl1);
                    MMA16816(acc[mt][nt], al[mt], bh0, bh1);
                }
            }
        }
        __syncthreads();
        if (c + 2 < nch) LOAD_STAGE(s, (c + 2) * 32);
    }
    #undef LOAD_STAGE

    // ---- epilogue ----
    #pragma unroll
    for (int mt = 0; mt < 2; mt++) {
        int r0 = rowBase + warpM * 32 + mt * 16 + g;
        int r1 = r0 + 8;
        float g0 = 0.f, g1v = 0.f;
        if (EPI == 1) { g0 = gate[r0]; g1v = gate[r1]; }
        #pragma unroll
        for (int nt = 0; nt < 8; nt++) {
            int col = colBase + warpN * 64 + nt * 8 + tg * 2;
            float d0 = acc[mt][nt][0], d1 = acc[mt][nt][1];
            float d2 = acc[mt][nt][2], d3 = acc[mt][nt][3];
            if (EPI == 0) {
                bf16* C0 = (bf16*)C0v; bf16* C1 = (bf16*)C1v;
                bf16 h0, l0, h1, l1;
                bf16_split(d0, h0, l0); bf16_split(d1, h1, l1);
                *(__nv_bfloat162*)(C0 + (size_t)r0 * ldc + col) = __nv_bfloat162(h0, h1);
                *(__nv_bfloat162*)(C1 + (size_t)r0 * ldc + col) = __nv_bfloat162(l0, l1);
                bf16_split(d2, h0, l0); bf16_split(d3, h1, l1);
                *(__nv_bfloat162*)(C0 + (size_t)r1 * ldc + col) = __nv_bfloat162(h0, h1);
                *(__nv_bfloat162*)(C1 + (size_t)r1 * ldc + col) = __nv_bfloat162(l0, l1);
            } else {
                float* C0 = (float*)C0v;
                float a0 = e0[col], a1 = e0[col + 1];
                if (EPI == 1) {
                    float p0 = e1[col], p1 = e1[col + 1];
                    *(float2*)(C0 + (size_t)r0 * ldc + col) = make_float2(d0 + a0 + g0 * p0,  d1 + a1 + g0 * p1);
                    *(float2*)(C0 + (size_t)r1 * ldc + col) = make_float2(d2 + a0 + g1v * p0, d3 + a1 + g1v * p1);
                } else {
                    *(float2*)(C0 + (size_t)r0 * ldc + col) = make_float2(d0 + a0, d1 + a1);
                    *(float2*)(C0 + (size_t)r1 * ldc + col) = make_float2(d2 + a0, d3 + a1);
                }
            }
        }
    }
}

// ---------------------------------------------------------------------------
// K3: scores -> softmax -> weights/entropy; u (bf16 split)
// ---------------------------------------------------------------------------
__global__ __launch_bounds__(256)
void attend_kernel(const float* __restrict__ ES, const float* __restrict__ r,
                   const float* __restrict__ sbias,
                   float* __restrict__ w_out, float* __restrict__ ent_out,
                   bf16* __restrict__ uh_out, bf16* __restrict__ ul_out) {
    const int b = blockIdx.x;
    const int tid = threadIdx.x;
    __shared__ float es_sh[6 * 1024];
    __shared__ float red[6][8];

    const float4* src = (const float4*)(ES + (size_t)b * 6 * 1024);
    float4* dst = (float4*)es_sh;
    #pragma unroll
    for (int i = 0; i < 6; i++) dst[tid + i * 256] = src[tid + i * 256];
    float4 rv = ((const float4*)(r + (size_t)b * 1024))[tid];
    __syncthreads();

    float4 ev[6];
    float sc[6];
    #pragma unroll
    for (int s = 0; s < 6; s++) {
        ev[s] = *(const float4*)&es_sh[s * 1024 + tid * 4];
        sc[s] = ev[s].x * rv.x + ev[s].y * rv.y + ev[s].z * rv.z + ev[s].w * rv.w;
    }
    #pragma unroll
    for (int s = 0; s < 6; s++)
        for (int o = 16; o; o >>= 1) sc[s] += __shfl_xor_sync(0xFFFFFFFFu, sc[s], o);
    if ((tid & 31) == 0) {
        #pragma unroll
        for (int s = 0; s < 6; s++) red[s][tid >> 5] = sc[s];
    }
    __syncthreads();

    float w[6], m = -1e30f;
    #pragma unroll
    for (int s = 0; s < 6; s++) {
        float t = sbias[s];
        #pragma unroll
        for (int wp = 0; wp < 8; wp++) t += red[s][wp];
        w[s] = t; m = fmaxf(m, t);
    }
    float Z = 0.f;
    #pragma unroll
    for (int s = 0; s < 6; s++) { w[s] = expf(w[s] - m); Z += w[s]; }
    float inv = 1.f / Z, ent = 0.f;
    #pragma unroll
    for (int s = 0; s < 6; s++) { w[s] *= inv; ent -= w[s] * logf(w[s] + 1e-8f); }
    if (tid == 0) {
        #pragma unroll
        for (int s = 0; s < 6; s++) w_out[(size_t)b * 6 + s] = w[s];
        ent_out[b] = ent;
    }

    float4 u;
    u.x = w[0]*ev[0].x; u.y = w[0]*ev[0].y; u.z = w[0]*ev[0].z; u.w = w[0]*ev[0].w;
    #pragma unroll
    for (int s = 1; s < 6; s++) {
        u.x += w[s]*ev[s].x; u.y += w[s]*ev[s].y; u.z += w[s]*ev[s].z; u.w += w[s]*ev[s].w;
    }
    bf16 hx, lx, hy, ly, hz, lz, hw, lw;
    bf16_split(u.x, hx, lx); bf16_split(u.y, hy, ly);
    bf16_split(u.z, hz, lz); bf16_split(u.w, hw, lw);
    size_t o = (size_t)b * 1024 + tid * 4;
    *(__nv_bfloat162*)(uh_out + o)     = __nv_bfloat162(hx, hy);
    *(__nv_bfloat162*)(uh_out + o + 2) = __nv_bfloat162(hz, hw);
    *(__nv_bfloat162*)(ul_out + o)     = __nv_bfloat162(lx, ly);
    *(__nv_bfloat162*)(ul_out + o + 2) = __nv_bfloat162(lz, lw);
}

// ---------------------------------------------------------------------------
// Host
// ---------------------------------------------------------------------------
static const int GEMM_SMEM = 2 * 4 * 128 * SROW * 2;   // 81920 B

extern "C" void kernel_launch(void* const* d_in, const int* in_sizes, int n_in,
                              void* d_out, int out_size) {
    const float* ES    = (const float*)d_in[0];
    const float* gate  = (const float*)d_in[2];
    const float* Wk    = (const float*)d_in[3];
    const float* Wv    = (const float*)d_in[5];
    const float* bv    = (const float*)d_in[6];
    const float* Wq    = (const float*)d_in[7];
    const float* bq    = (const float*)d_in[8];
    const float* Wp    = (const float*)d_in[9];
    const float* bp    = (const float*)d_in[10];
    const float* sbias = (const float*)d_in[11];

    const int B = in_sizes[2];    // [B,1]
    const int H = in_sizes[4];    // [H]
    const int S = in_sizes[11];   // [S]

    float* out       = (float*)d_out;
    float* out_fused = out;
    float* out_w     = out + (size_t)B * H;
    float* out_ent   = out_w + (size_t)B * S;

    bf16 *ch, *cl, *wkh, *wkl, *wqh, *wql, *wth, *wtl, *vth, *vtl, *uh, *ul;
    float *rr, *cp, *pp;
    cudaGetSymbolAddress((void**)&ch,  g_cond_hi);
    cudaGetSymbolAddress((void**)&cl,  g_cond_lo);
    cudaGetSymbolAddress((void**)&wkh, g_Wk_hi);
    cudaGetSymbolAddress((void**)&wkl, g_Wk_lo);
    cudaGetSymbolAddress((void**)&wqh, g_Wq_hi);
    cudaGetSymbolAddress((void**)&wql, g_Wq_lo);
    cudaGetSymbolAddress((void**)&wth, g_Wt_hi);
    cudaGetSymbolAddress((void**)&wtl, g_Wt_lo);
    cudaGetSymbolAddress((void**)&vth, g_WvT_hi);
    cudaGetSymbolAddress((void**)&vtl, g_WvT_lo);
    cudaGetSymbolAddress((void**)&uh,  g_u_hi);
    cudaGetSymbolAddress((void**)&ul,  g_u_lo);
    cudaGetSymbolAddress((void**)&rr,  g_r);
    cudaGetSymbolAddress((void**)&cp,  g_cp);
    cudaGetSymbolAddress((void**)&pp,  g_pp);

    cudaFuncSetAttribute(mma_gemm<0>, cudaFuncAttributeMaxDynamicSharedMemorySize, GEMM_SMEM);
    cudaFuncSetAttribute(mma_gemm<1>, cudaFuncAttributeMaxDynamicSharedMemorySize, GEMM_SMEM);
    cudaFuncSetAttribute(mma_gemm<2>, cudaFuncAttributeMaxDynamicSharedMemorySize, GEMM_SMEM);

    // producers
    pool_kernel<<<(B * H + 255) / 256, 256>>>(ES, ch, cl, B, S, H);
    fold_kernel<<<(H * 32 + 255) / 256, 256>>>(Wk, bq, bp, Wp, cp, pp, H);
    split_kernel<<<(H * H + 255) / 256, 256>>>(Wk, wkh, wkl, H * H);
    split_kernel<<<(2 * H * H + 255) / 256, 256>>>(Wq, wqh, wql, 2 * H * H);
    {
        dim3 g(H / 32, H / 32), blk(32, 8);
        transpose_split_kernel<<<g, blk>>>(Wv, vth, vtl, H);
    }
    // K1: Wt[m,n] = sum_j Wk[m,j]*Wq[n,j]  -> [H, 2H], split epilogue
    {
        dim3 grid((2 * H) / 128, H / 128);
        mma_gemm<0><<<grid, 256, GEMM_SMEM>>>(wkh, wkl, wqh, wql,
            wth, wtl, 2 * H, H, nullptr, nullptr, nullptr);
    }
    // K2: r[b,h] = sum_i cond[b,i]*Wt[h,i] + cp[h] + gate[b]*pp[h]
    {
        dim3 grid(H / 128, B / 128);
        mma_gemm<1><<<grid, 256, GEMM_SMEM>>>(ch, cl, wth, wtl,
            rr, nullptr, H, 2 * H, cp, pp, gate);
    }
    // K3: softmax/entropy + u split
    attend_kernel<<<B, 256>>>(ES, rr, sbias, out_w, out_ent, uh, ul);
    // K4: fused[b,j] = sum_h u[b,h]*WvT[j,h] + bv[j]
    {
        dim3 grid(H / 128, B / 128);
        mma_gemm<2><<<grid, 256, GEMM_SMEM>>>(uh, ul, vth, vtl,
            out_fused, nullptr, H, H, bv, nullptr, nullptr);
    }
}